// round 14
// baseline (speedup 1.0000x reference)
#include <cuda_runtime.h>
#include <cuda_fp16.h>
#include <cstdint>
#include <math.h>

// Problem dims
#define M_DIM 16
#define VN    8192
#define DIN   512
#define DOUT  512
#define ROWS  (M_DIM * VN)              // 131072
#define NPER  (VN * DIN)                // 4194304 per m-slice
#define NPER4 (NPER / 4)

#define GRAM_CTAS   1024
#define PART_STRIDE 272                 // 256 G partials + 16 sq partials
#define PRE_GROUPS  64

// -------------------- scratch --------------------
__device__ __half g_Xh[(size_t)ROWS * DIN];   // fp16 X
__device__ __half g_Wqh[(size_t)DOUT * DIN];  // fp16 weights
__device__ __half g_Wkh[(size_t)DOUT * DIN];
__device__ __half g_Wvh[(size_t)DOUT * DIN];
__device__ __half g_Uh[(size_t)ROWS * DOUT];  // U = X Wv^T + bv (fp16)
__device__ float g_part[GRAM_CTAS * PART_STRIDE];
__device__ float g_part2[PRE_GROUPS * PART_STRIDE];
__device__ float g_P[256];

// -------------------- helpers --------------------
__device__ __forceinline__ void mma_f16(float c[4], const uint32_t a[4],
                                        uint32_t b0, uint32_t b1) {
    asm volatile(
        "mma.sync.aligned.m16n8k16.row.col.f32.f16.f16.f32 "
        "{%0,%1,%2,%3}, {%4,%5,%6,%7}, {%8,%9}, {%0,%1,%2,%3};\n"
        : "+f"(c[0]), "+f"(c[1]), "+f"(c[2]), "+f"(c[3])
        : "r"(a[0]), "r"(a[1]), "r"(a[2]), "r"(a[3]), "r"(b0), "r"(b1));
}

__device__ __forceinline__ uint32_t sptr(const void* p) {
    return (uint32_t)__cvta_generic_to_shared(p);
}
__device__ __forceinline__ void cpa16(uint32_t s, const void* g) {
    asm volatile("cp.async.ca.shared.global [%0], [%1], 16;\n" :: "r"(s), "l"(g));
}
#define CP_COMMIT()  asm volatile("cp.async.commit_group;\n")
#define CP_WAIT2()   asm volatile("cp.async.wait_group 2;\n")
#define CP_WAIT1()   asm volatile("cp.async.wait_group 1;\n")
#define CP_WAIT0()   asm volatile("cp.async.wait_group 0;\n")

__device__ __forceinline__ void ldsm_x4(uint32_t r[4], uint32_t saddr) {
    asm volatile("ldmatrix.sync.aligned.m8n8.x4.shared.b16 {%0,%1,%2,%3}, [%4];"
        : "=r"(r[0]), "=r"(r[1]), "=r"(r[2]), "=r"(r[3]) : "r"(saddr));
}

__device__ __forceinline__ uint32_t hpack(float a, float b) {
    __half2 h = __floats2half2_rn(a, b);
    return *(uint32_t*)&h;
}
__device__ __forceinline__ uint32_t ldh2(const __half* p) {
    return *(const uint32_t*)p;
}

// steady-state wait for 4-stage pipeline with 3 groups in flight
__device__ __forceinline__ void cp_wait_tail(int kt, int last) {
    if (kt <= last - 3)      { CP_WAIT2(); }
    else if (kt == last - 2) { CP_WAIT2(); }
    else if (kt == last - 1) { CP_WAIT1(); }
    else                     { CP_WAIT0(); }
}

// -------------------- prep: convert X to fp16 --------------------
__global__ void cvtX_kernel(const float4* __restrict__ X)
{
    size_t i = (size_t)blockIdx.x * 256 + threadIdx.x;   // over ROWS*DIN/4
    float4 v = X[i];
    uint2 h;
    h.x = hpack(v.x, v.y);
    h.y = hpack(v.z, v.w);
    ((uint2*)g_Xh)[i] = h;
}

// -------------------- prep: convert the 3 weight matrices --------------------
__global__ void cvtW_kernel(const float4* __restrict__ wq,
                            const float4* __restrict__ wk,
                            const float4* __restrict__ wv)
{
    int i = blockIdx.x * 256 + threadIdx.x;              // 0..65535
    const float4* s = (blockIdx.y == 0) ? wq : (blockIdx.y == 1) ? wk : wv;
    uint2* d = (blockIdx.y == 0) ? (uint2*)g_Wqh
             : (blockIdx.y == 1) ? (uint2*)g_Wkh : (uint2*)g_Wvh;
    float4 v = s[i];
    uint2 h;
    h.x = hpack(v.x, v.y);
    h.y = hpack(v.z, v.w);
    d[i] = h;
}

// ============================================================================
// K1: fused QK projections (fp16) + Gram + fro, 256 threads.
// Group 0 (warps 0-3) = Q, group 1 (warps 4-7) = K; each group covers its
// 128x128 tile with 2x2 warps of 64x64.
// 4-stage cp.async (3 groups in flight), k-tile = 32 halves.
// Stage: A 0, Bq 10240, Bk 20480; stage 30720 B (x4 = 122880 B).
// Epilogue union (within stage space): QTh (half, stride 140) at 0,
// KTh at 35840, RED (4x256 fp32) + RED2 (128 fp32) at 71680.
// ============================================================================
#define K1_STAGE_B  30720
#define K1_KTB_OFF  35840
#define K1_REDB_OFF 71680
#define K1_BYTES    (4 * K1_STAGE_B)
#define QK_STR      140                 // halves per staged row (conflict-free)

__global__ void __launch_bounds__(256, 1) qkgram_kernel(
    const float* __restrict__ biasq, const float* __restrict__ biask)
{
    extern __shared__ float S[];
    __half* QTh = (__half*)S;
    __half* KTh = (__half*)((char*)S + K1_KTB_OFF);
    const uint32_t smemu = sptr(S);

    const int tid  = threadIdx.x;
    const int lane = tid & 31;
    const int wid  = tid >> 5;      // 0..7
    const int wg   = wid >> 2;      // 0 = Q, 1 = K
    const int wl   = wid & 3;       // warp in group
    const int gid  = lane >> 2;
    const int tig  = lane & 3;
    const int wm   = wl & 1;        // 2 m-tiles x 64 rows
    const int wn   = wl >> 1;       // 2 n-tiles x 64 cols
    const int v0   = blockIdx.x * 8;

    const int lofsB = (lane & 15) * 80 + ((lane >> 4) << 4);   // bytes

    const float* bias = wg ? biask : biasq;
    __half*      OTh  = wg ? KTh : QTh;

    float Gc[2][4] = {{0.f,0.f,0.f,0.f},{0.f,0.f,0.f,0.f}};
    float facc = 0.f;
    float acc[4][8][4];

    for (int ct = 0; ct < 4; ++ct) {
        const int n0 = ct * 128;
#pragma unroll
        for (int a = 0; a < 4; a++)
#pragma unroll
            for (int b = 0; b < 8; b++)
#pragma unroll
                for (int c = 0; c < 4; c++) acc[a][b][c] = 0.f;

        auto issue = [&](int kt, int st) {
            uint32_t base = smemu + st * K1_STAGE_B;
#pragma unroll
            for (int it = 0; it < 2; ++it) {
                int idx = tid + it * 256;       // 0..511
                int cr  = idx >> 2;             // 0..127
                int cc  = (idx & 3) * 16;
                int grow = (cr >> 3) * VN + v0 + (cr & 7);
                uint32_t d = base + cr * 80 + cc;
                size_t xo = (size_t)grow * (DIN * 2) + kt * 64 + cc;
                size_t wo = (size_t)(n0 + cr) * (DIN * 2) + kt * 64 + cc;
                cpa16(d,         (const char*)g_Xh  + xo);
                cpa16(d + 10240, (const char*)g_Wqh + wo);
                cpa16(d + 20480, (const char*)g_Wkh + wo);
            }
        };

        issue(0, 0); CP_COMMIT();
        issue(1, 1); CP_COMMIT();
        issue(2, 2); CP_COMMIT();
#pragma unroll 1
        for (int kt = 0; kt < 16; ++kt) {
            cp_wait_tail(kt, 15);
            __syncthreads();
            if (kt + 3 < 16) { issue(kt + 3, (kt + 3) & 3); CP_COMMIT(); }
            const uint32_t stage = smemu + (kt & 3) * K1_STAGE_B;
            const uint32_t aB = stage + lofsB;
            const uint32_t bB = stage + (wg ? 20480 : 10240) + lofsB;
#pragma unroll
            for (int ks = 0; ks < 2; ++ks) {
                const int kb = ks * 32;
                uint32_t ah[4][4];
#pragma unroll
                for (int mf = 0; mf < 4; ++mf)
                    ldsm_x4(ah[mf], aB + (wm * 64 + mf * 16) * 80 + kb);
#pragma unroll
                for (int p = 0; p < 4; ++p) {
                    uint32_t bh[4];
                    ldsm_x4(bh, bB + (wn * 64 + p * 16) * 80 + kb);
#pragma unroll
                    for (int mf = 0; mf < 4; ++mf) {
                        mma_f16(acc[mf][2*p],     ah[mf], bh[0], bh[2]);
                        mma_f16(acc[mf][2*p + 1], ah[mf], bh[1], bh[3]);
                    }
                }
            }
        }
        __syncthreads();   // compute done before staging over pipeline bufs

        // Stage projected tile (+bias) as fp16
#pragma unroll
        for (int nf = 0; nf < 8; ++nf) {
            int col = wn * 64 + nf * 8 + tig * 2;
            float b0 = bias[n0 + col], b1 = bias[n0 + col + 1];
#pragma unroll
            for (int mf = 0; mf < 4; ++mf) {
                int r0 = wm * 64 + mf * 16 + gid;
                *(__half2*)&OTh[r0 * QK_STR + col] =
                    __floats2half2_rn(acc[mf][nf][0] + b0, acc[mf][nf][1] + b1);
                *(__half2*)&OTh[(r0 + 8) * QK_STR + col] =
                    __floats2half2_rn(acc[mf][nf][2] + b0, acc[mf][nf][3] + b1);
            }
        }
        __syncthreads();

        if (wg == 0) {
            // Gram via fp16 MMA: Q-warp wl handles dv = wl and wl+4
#pragma unroll
            for (int dvi = 0; dvi < 2; ++dvi) {
                const int dv = wl + dvi * 4;
#pragma unroll
                for (int kk = 0; kk < 8; ++kk) {
                    const int kb = kk * 16 + tig * 2;
                    uint32_t a[4];
                    a[0] = ldh2(&QTh[(gid * 8 + dv)       * QK_STR + kb]);
                    a[1] = ldh2(&QTh[((gid + 8) * 8 + dv) * QK_STR + kb]);
                    a[2] = ldh2(&QTh[(gid * 8 + dv)       * QK_STR + kb + 8]);
                    a[3] = ldh2(&QTh[((gid + 8) * 8 + dv) * QK_STR + kb + 8]);
                    uint32_t b0 = ldh2(&KTh[(gid * 8 + dv) * QK_STR + kb]);
                    uint32_t b1 = ldh2(&KTh[(gid * 8 + dv) * QK_STR + kb + 8]);
                    mma_f16(Gc[0], a, b0, b1);
                    b0 = ldh2(&KTh[((gid + 8) * 8 + dv) * QK_STR + kb]);
                    b1 = ldh2(&KTh[((gid + 8) * 8 + dv) * QK_STR + kb + 8]);
                    mma_f16(Gc[1], a, b0, b1);
                }
            }
        } else {
            // fro: ||Q||^2 partial (one full row per thread)
            int r = tid - 128;   // 0..127
#pragma unroll 8
            for (int c = 0; c < 64; ++c) {
                __half2 h = *(const __half2*)&QTh[r * QK_STR + 2 * c];
                float2 f = __half22float2(h);
                facc += f.x * f.x + f.y * f.y;
            }
        }
        __syncthreads();
    }

    float* RED  = (float*)((char*)S + K1_REDB_OFF);   // 4 x 256
    float* RED2 = RED + 1024;                          // 128
    if (wg == 0) {
        RED[wl * 256 + gid * 16 + 2 * tig]               = Gc[0][0];
        RED[wl * 256 + gid * 16 + 2 * tig + 1]           = Gc[0][1];
        RED[wl * 256 + (gid + 8) * 16 + 2 * tig]         = Gc[0][2];
        RED[wl * 256 + (gid + 8) * 16 + 2 * tig + 1]     = Gc[0][3];
        RED[wl * 256 + gid * 16 + 8 + 2 * tig]           = Gc[1][0];
        RED[wl * 256 + gid * 16 + 8 + 2 * tig + 1]       = Gc[1][1];
        RED[wl * 256 + (gid + 8) * 16 + 8 + 2 * tig]     = Gc[1][2];
        RED[wl * 256 + (gid + 8) * 16 + 8 + 2 * tig + 1] = Gc[1][3];
    } else {
        RED2[tid - 128] = facc;
    }
    __syncthreads();
    {
        float g = 0.f;
#pragma unroll
        for (int w = 0; w < 4; ++w) g += RED[w * 256 + tid];
        g_part[(size_t)blockIdx.x * PART_STRIDE + tid] = g;
    }
    if (tid < 16) {
        float s = 0.f;
#pragma unroll
        for (int t = 0; t < 8; ++t) s += RED2[tid * 8 + t];
        g_part[(size_t)blockIdx.x * PART_STRIDE + 256 + tid] = s;
    }
}

// ============================================================================
// K2: U = X Wv^T + bv  (fp16 in/out, 256 threads, 4x2 warps of 32x64,
// 4-stage cp.async (3 in flight), 2 CTAs/SM).
// Stage: A 0, B 10240; size 20480 (x4 = 81920 B; 2 CTAs = 160 KB < 227 KB).
// ============================================================================
#define V_STAGE_B  20480
#define V_BYTES    (4 * V_STAGE_B)

__global__ void __launch_bounds__(256, 2) gemm_v(const float* __restrict__ bias)
{
    extern __shared__ float S[];
    const uint32_t smemu = sptr(S);

    const int tid  = threadIdx.x;
    const int lane = tid & 31;
    const int wid  = tid >> 5;      // 0..7
    const int gid  = lane >> 2;
    const int tig  = lane & 3;
    const int wm   = wid & 3;       // 4 m-tiles x 32 rows
    const int wn   = wid >> 2;      // 2 n-tiles x 64 cols
    const int m0   = blockIdx.y * 128;
    const int n0   = blockIdx.x * 128;

    const int lofsB = (lane & 15) * 80 + ((lane >> 4) << 4);

    float acc[2][8][4];
#pragma unroll
    for (int a = 0; a < 2; a++)
#pragma unroll
        for (int b = 0; b < 8; b++)
#pragma unroll
            for (int c = 0; c < 4; c++) acc[a][b][c] = 0.f;

    auto issue = [&](int kt, int st) {
        uint32_t d0 = smemu + st * V_STAGE_B;
#pragma unroll
        for (int it = 0; it < 2; ++it) {
            int idx = tid + it * 256;       // 0..511
            int cr  = idx >> 2;             // 0..127
            int cc  = (idx & 3) * 16;
            uint32_t d = d0 + cr * 80 + cc;
            size_t xo = (size_t)(m0 + cr) * (DIN * 2) + kt * 64 + cc;
            size_t wo = (size_t)(n0 + cr) * (DIN * 2) + kt * 64 + cc;
            cpa16(d,         (const char*)g_Xh  + xo);
            cpa16(d + 10240, (const char*)g_Wvh + wo);
        }
    };

    issue(0, 0); CP_COMMIT();
    issue(1, 1); CP_COMMIT();
    issue(2, 2); CP_COMMIT();
#pragma unroll 1
    for (int kt = 0; kt < 16; ++kt) {
        cp_wait_tail(kt, 15);
        __syncthreads();
        if (kt + 3 < 16) { issue(kt + 3, (kt + 3) & 3); CP_COMMIT(); }
        const uint32_t stage = smemu + (kt & 3) * V_STAGE_B;
        const uint32_t aB = stage + lofsB;
        const uint32_t bB = stage + 10240 + lofsB;
#pragma unroll
        for (int ks = 0; ks < 2; ++ks) {
            const int kb = ks * 32;
            uint32_t ah[2][4];
            ldsm_x4(ah[0], aB + (wm * 32)      * 80 + kb);
            ldsm_x4(ah[1], aB + (wm * 32 + 16) * 80 + kb);
#pragma unroll
            for (int p = 0; p < 4; ++p) {
                uint32_t bh[4];
                ldsm_x4(bh, bB + (wn * 64 + p * 16) * 80 + kb);
#pragma unroll
                for (int mf = 0; mf < 2; ++mf) {
                    mma_f16(acc[mf][2*p],     ah[mf], bh[0], bh[2]);
                    mma_f16(acc[mf][2*p + 1], ah[mf], bh[1], bh[3]);
                }
            }
        }
    }

#pragma unroll
    for (int nf = 0; nf < 8; ++nf) {
        int col = n0 + wn * 64 + nf * 8 + tig * 2;
        float b0 = bias[col];
        float b1 = bias[col + 1];
#pragma unroll
        for (int mf = 0; mf < 2; ++mf) {
            int r0 = m0 + wm * 32 + mf * 16 + gid;
            *(__half2*)(g_Uh + (size_t)r0 * DOUT + col) =
                __floats2half2_rn(acc[mf][nf][0] + b0, acc[mf][nf][1] + b1);
            *(__half2*)(g_Uh + (size_t)(r0 + 8) * DOUT + col) =
                __floats2half2_rn(acc[mf][nf][2] + b0, acc[mf][nf][3] + b1);
        }
    }
}

// ============================================================================
// K3a: pre-reduce partials 1024 -> 64 groups (deterministic)
// ============================================================================
__global__ void __launch_bounds__(288) prereduce_kernel()
{
    int tid = threadIdx.x;
    if (tid >= PART_STRIDE) return;
    int b = blockIdx.x;
    float s = 0.f;
#pragma unroll 4
    for (int c = 0; c < 16; ++c)
        s += g_part[(size_t)(b * 16 + c) * PART_STRIDE + tid];
    g_part2[b * PART_STRIDE + tid] = s;
}

// ============================================================================
// K3b: finalize — reduce 64 groups, sigmoid, dual softmax, 10x projection -> P
// ============================================================================
__global__ void __launch_bounds__(256) finalize_kernel()
{
    __shared__ float Am[256], T[256], FR[256];
    __shared__ float fro[16], m0s[16], s0s[16], m1s[16], s1s[16], red[16], red2[16];
    const int tid = threadIdx.x;
    const int i = tid >> 4, j = tid & 15;

    float a0=0,a1=0,a2=0,a3=0,a4=0,a5=0,a6=0,a7=0;
    for (int c = 0; c < PRE_GROUPS; c += 8) {
        a0 += g_part2[(size_t)(c    ) * PART_STRIDE + tid];
        a1 += g_part2[(size_t)(c + 1) * PART_STRIDE + tid];
        a2 += g_part2[(size_t)(c + 2) * PART_STRIDE + tid];
        a3 += g_part2[(size_t)(c + 3) * PART_STRIDE + tid];
        a4 += g_part2[(size_t)(c + 4) * PART_STRIDE + tid];
        a5 += g_part2[(size_t)(c + 5) * PART_STRIDE + tid];
        a6 += g_part2[(size_t)(c + 6) * PART_STRIDE + tid];
        a7 += g_part2[(size_t)(c + 7) * PART_STRIDE + tid];
    }
    float g = ((a0 + a1) + (a2 + a3)) + ((a4 + a5) + (a6 + a7));

    {
        float s = 0.f;
        for (int c = i * 4; c < i * 4 + 4; ++c)
            s += g_part2[(size_t)c * PART_STRIDE + 256 + j];
        FR[tid] = s;
    }
    __syncthreads();
    if (tid < 16) {
        float s = 0.f;
#pragma unroll
        for (int t = 0; t < 16; ++t) s += FR[t * 16 + tid];
        fro[tid] = sqrtf(s);
    }
    __syncthreads();

    float p0 = 1.f / (1.f + expf(-g / fro[i]));
    Am[tid] = p0;
    __syncthreads();

    if (tid < 16) {
        float m = -1e30f;
        for (int k = 0; k < 16; ++k) m = fmaxf(m, Am[k * 16 + tid]);
        float s = 0.f;
        for (int k = 0; k < 16; ++k) s += expf(Am[k * 16 + tid] - m);
        m0s[tid] = m; s0s[tid] = s;
        float m1 = -1e30f;
        for (int k = 0; k < 16; ++k) m1 = fmaxf(m1, Am[tid * 16 + k]);
        float s1 = 0.f;
        for (int k = 0; k < 16; ++k) s1 += expf(Am[tid * 16 + k] - m1);
        m1s[tid] = m1; s1s[tid] = s1;
    }
    __syncthreads();

    float p = 0.5f * (expf(p0 - m0s[j]) / s0s[j] + expf(p0 - m1s[i]) / s1s[i]);

    for (int it = 0; it < 10; ++it) {
        float p1 = fmaxf(p, 0.f);
        T[tid] = p1;
        __syncthreads();
        if (tid < 16) {
            float s = 0.f;
            for (int k = 0; k < 16; ++k) s += T[tid * 16 + k];
            red[tid] = (s - 1.f) * (1.f / 16.f);
        }
        __syncthreads();
        float p2 = p1 - red[i];
        T[tid] = p2;
        __syncthreads();
        if (tid < 16) {
            float s = 0.f;
            for (int k = 0; k < 16; ++k) s += T[k * 16 + tid];
            red2[tid] = (s - 1.f) * (1.f / 16.f);
        }
        __syncthreads();
        p = p2 - red2[j];
        __syncthreads();
    }
    g_P[tid] = p;
}

// ============================================================================
// K4: out[j] = sum_i P[i,j] * U[i]   (U fp16, accumulate fp32, out fp32)
// ============================================================================
__global__ void __launch_bounds__(256) mix_kernel(float* __restrict__ out)
{
    __shared__ float Ps[256];
    Ps[threadIdx.x] = g_P[threadIdx.x];
    __syncthreads();

    size_t n4 = (size_t)blockIdx.x * 256 + threadIdx.x;   // 0..NPER4-1
    const uint2* U2 = (const uint2*)g_Uh;                 // 4 halves per elem
    float4* O4 = (float4*)out;

    float4 x[16];
#pragma unroll
    for (int i = 0; i < 16; ++i) {
        uint2 h = U2[(size_t)i * NPER4 + n4];
        float2 lo = __half22float2(*(__half2*)&h.x);
        float2 hi = __half22float2(*(__half2*)&h.y);
        x[i] = make_float4(lo.x, lo.y, hi.x, hi.y);
    }
#pragma unroll
    for (int jj = 0; jj < 16; ++jj) {
        float4 y = make_float4(0.f, 0.f, 0.f, 0.f);
#pragma unroll
        for (int i = 0; i < 16; ++i) {
            float pv = Ps[i * 16 + jj];
            y.x += pv * x[i].x; y.y += pv * x[i].y;
            y.z += pv * x[i].z; y.w += pv * x[i].w;
        }
        O4[(size_t)jj * NPER4 + n4] = y;
    }
}

// -------------------- launch --------------------
extern "C" void kernel_launch(void* const* d_in, const int* in_sizes, int n_in,
                              void* d_out, int out_size)
{
    const float* X   = (const float*)d_in[0];
    const float* WQw = (const float*)d_in[1];
    const float* WQb = (const float*)d_in[2];
    const float* WKw = (const float*)d_in[3];
    const float* WKb = (const float*)d_in[4];
    const float* WVw = (const float*)d_in[5];
    const float* WVb = (const float*)d_in[6];
    float* out = (float*)d_out;

    cudaFuncSetAttribute(qkgram_kernel,
                         cudaFuncAttributeMaxDynamicSharedMemorySize, K1_BYTES);
    cudaFuncSetAttribute(gemm_v,
                         cudaFuncAttributeMaxDynamicSharedMemorySize, V_BYTES);

    // Convert X and weights to fp16
    cvtX_kernel<<<ROWS * DIN / 4 / 256, 256>>>((const float4*)X);
    cvtW_kernel<<<dim3(256, 3), 256>>>((const float4*)WQw,
                                       (const float4*)WKw,
                                       (const float4*)WVw);

    // Fused Q/K projections (fp16, 64x64 warp tiles, 4-stage) + Gram + fro
    qkgram_kernel<<<GRAM_CTAS, 256, K1_BYTES>>>(WQb, WKb);

    // U = X Wv^T + bv (fp16 in/out, 32x64 warp tiles, 4-stage, 2 CTAs/SM)
    gemm_v<<<dim3(DOUT / 128, ROWS / 128), 256, V_BYTES>>>(WVb);

    // P
    prereduce_kernel<<<PRE_GROUPS, 288>>>();
    finalize_kernel<<<1, 256>>>();

    // out[j] = sum_i P[ij] U[i]
    mix_kernel<<<NPER4 / 256, 256>>>(out);
}

// round 15
// speedup vs baseline: 1.0100x; 1.0100x over previous
#include <cuda_runtime.h>
#include <cuda_fp16.h>
#include <cstdint>
#include <math.h>

// Problem dims
#define M_DIM 16
#define VN    8192
#define DIN   512
#define DOUT  512
#define ROWS  (M_DIM * VN)              // 131072
#define NPER  (VN * DIN)                // 4194304 per m-slice
#define NPER4 (NPER / 4)

#define GRAM_CTAS   1024
#define PART_STRIDE 272                 // 256 G partials + 16 sq partials
#define PRE_GROUPS  64

// -------------------- scratch --------------------
__device__ __half g_Xh[(size_t)ROWS * DIN];   // fp16 X
__device__ __half g_Wqh[(size_t)DOUT * DIN];  // fp16 weights
__device__ __half g_Wkh[(size_t)DOUT * DIN];
__device__ __half g_Wvh[(size_t)DOUT * DIN];
__device__ __half g_Uh[(size_t)ROWS * DOUT];  // U = X Wv^T + bv (fp16)
__device__ float g_part[GRAM_CTAS * PART_STRIDE];
__device__ float g_part2[PRE_GROUPS * PART_STRIDE];
__device__ float g_P[256];

// -------------------- helpers --------------------
__device__ __forceinline__ void mma_f16(float c[4], const uint32_t a[4],
                                        uint32_t b0, uint32_t b1) {
    asm volatile(
        "mma.sync.aligned.m16n8k16.row.col.f32.f16.f16.f32 "
        "{%0,%1,%2,%3}, {%4,%5,%6,%7}, {%8,%9}, {%0,%1,%2,%3};\n"
        : "+f"(c[0]), "+f"(c[1]), "+f"(c[2]), "+f"(c[3])
        : "r"(a[0]), "r"(a[1]), "r"(a[2]), "r"(a[3]), "r"(b0), "r"(b1));
}

__device__ __forceinline__ uint32_t sptr(const void* p) {
    return (uint32_t)__cvta_generic_to_shared(p);
}
__device__ __forceinline__ void cpa16(uint32_t s, const void* g) {
    asm volatile("cp.async.ca.shared.global [%0], [%1], 16;\n" :: "r"(s), "l"(g));
}
#define CP_COMMIT()  asm volatile("cp.async.commit_group;\n")
#define CP_WAIT1()   asm volatile("cp.async.wait_group 1;\n")
#define CP_WAIT0()   asm volatile("cp.async.wait_group 0;\n")

__device__ __forceinline__ void ldsm_x4(uint32_t r[4], uint32_t saddr) {
    asm volatile("ldmatrix.sync.aligned.m8n8.x4.shared.b16 {%0,%1,%2,%3}, [%4];"
        : "=r"(r[0]), "=r"(r[1]), "=r"(r[2]), "=r"(r[3]) : "r"(saddr));
}

__device__ __forceinline__ uint32_t hpack(float a, float b) {
    __half2 h = __floats2half2_rn(a, b);
    return *(uint32_t*)&h;
}
__device__ __forceinline__ uint32_t ldh2(const __half* p) {
    return *(const uint32_t*)p;
}

// -------------------- prep: convert X + the 3 weight matrices to fp16 -------
// 1D grid: blocks [0, 16384) handle X (ROWS*DIN/4 float4), tail 768 blocks
// handle the three 512x512 weight matrices (256 blocks each).
#define CVT_XBLKS (ROWS * DIN / 4 / 256)      // 16384
__global__ void cvt_all_kernel(const float4* __restrict__ X,
                               const float4* __restrict__ wq,
                               const float4* __restrict__ wk,
                               const float4* __restrict__ wv)
{
    int bid = blockIdx.x;
    if (bid < CVT_XBLKS) {
        size_t i = (size_t)bid * 256 + threadIdx.x;
        float4 v = X[i];
        uint2 h;
        h.x = hpack(v.x, v.y);
        h.y = hpack(v.z, v.w);
        ((uint2*)g_Xh)[i] = h;
    } else {
        int b2 = bid - CVT_XBLKS;            // 0..767
        int w  = b2 >> 8;                    // 0..2
        int i  = (b2 & 255) * 256 + threadIdx.x;
        const float4* s = (w == 0) ? wq : (w == 1) ? wk : wv;
        uint2* d = (w == 0) ? (uint2*)g_Wqh
                 : (w == 1) ? (uint2*)g_Wkh : (uint2*)g_Wvh;
        float4 v = s[i];
        uint2 h;
        h.x = hpack(v.x, v.y);
        h.y = hpack(v.z, v.w);
        d[i] = h;
    }
}

// ============================================================================
// K1: fused QK projections (fp16) + Gram + fro, 256 threads (R13 config).
// Group 0 (warps 0-3) = Q, group 1 (warps 4-7) = K; each group covers its
// 128x128 tile with 2x2 warps of 64x64.
// 3-stage cp.async, k-tile = 32 halves. Stage: A 0, Bq 10240, Bk 20480;
// stage 30720 B (x3 = 92160 B).
// Epilogue union: QTh (half, stride 140) at 0, KTh at 35840,
// RED (4x256 fp32) + RED2 (128 fp32) at 71680.
// ============================================================================
#define K1_STAGE_B  30720
#define K1_KTB_OFF  35840
#define K1_REDB_OFF 71680
#define K1_BYTES    92160
#define QK_STR      140                 // halves per staged row (conflict-free)

__global__ void __launch_bounds__(256, 1) qkgram_kernel(
    const float* __restrict__ biasq, const float* __restrict__ biask)
{
    extern __shared__ float S[];
    __half* QTh = (__half*)S;
    __half* KTh = (__half*)((char*)S + K1_KTB_OFF);
    const uint32_t smemu = sptr(S);

    const int tid  = threadIdx.x;
    const int lane = tid & 31;
    const int wid  = tid >> 5;      // 0..7
    const int wg   = wid >> 2;      // 0 = Q, 1 = K
    const int wl   = wid & 3;       // warp in group
    const int gid  = lane >> 2;
    const int tig  = lane & 3;
    const int wm   = wl & 1;        // 2 m-tiles x 64 rows
    const int wn   = wl >> 1;       // 2 n-tiles x 64 cols
    const int v0   = blockIdx.x * 8;

    const int lofsB = (lane & 15) * 80 + ((lane >> 4) << 4);   // bytes

    const float* bias = wg ? biask : biasq;
    __half*      OTh  = wg ? KTh : QTh;

    float Gc[2][4] = {{0.f,0.f,0.f,0.f},{0.f,0.f,0.f,0.f}};
    float facc = 0.f;
    float acc[4][8][4];

    for (int ct = 0; ct < 4; ++ct) {
        const int n0 = ct * 128;
#pragma unroll
        for (int a = 0; a < 4; a++)
#pragma unroll
            for (int b = 0; b < 8; b++)
#pragma unroll
                for (int c = 0; c < 4; c++) acc[a][b][c] = 0.f;

        auto issue = [&](int kt, int st) {
            uint32_t base = smemu + st * K1_STAGE_B;
#pragma unroll
            for (int it = 0; it < 2; ++it) {
                int idx = tid + it * 256;       // 0..511
                int cr  = idx >> 2;             // 0..127
                int cc  = (idx & 3) * 16;
                int grow = (cr >> 3) * VN + v0 + (cr & 7);
                uint32_t d = base + cr * 80 + cc;
                size_t xo = (size_t)grow * (DIN * 2) + kt * 64 + cc;
                size_t wo = (size_t)(n0 + cr) * (DIN * 2) + kt * 64 + cc;
                cpa16(d,         (const char*)g_Xh  + xo);
                cpa16(d + 10240, (const char*)g_Wqh + wo);
                cpa16(d + 20480, (const char*)g_Wkh + wo);
            }
        };

        issue(0, 0); CP_COMMIT();
        issue(1, 1); CP_COMMIT();
#pragma unroll 1
        for (int kt = 0; kt < 16; ++kt) {
            if (kt < 14) { CP_WAIT1(); } else { CP_WAIT0(); }
            __syncthreads();
            if (kt + 2 < 16) { issue(kt + 2, (kt + 2) % 3); CP_COMMIT(); }
            const uint32_t stage = smemu + (kt % 3) * K1_STAGE_B;
            const uint32_t aB = stage + lofsB;
            const uint32_t bB = stage + (wg ? 20480 : 10240) + lofsB;
#pragma unroll
            for (int ks = 0; ks < 2; ++ks) {
                const int kb = ks * 32;
                uint32_t ah[4][4];
#pragma unroll
                for (int mf = 0; mf < 4; ++mf)
                    ldsm_x4(ah[mf], aB + (wm * 64 + mf * 16) * 80 + kb);
#pragma unroll
                for (int p = 0; p < 4; ++p) {
                    uint32_t bh[4];
                    ldsm_x4(bh, bB + (wn * 64 + p * 16) * 80 + kb);
#pragma unroll
                    for (int mf = 0; mf < 4; ++mf) {
                        mma_f16(acc[mf][2*p],     ah[mf], bh[0], bh[2]);
                        mma_f16(acc[mf][2*p + 1], ah[mf], bh[1], bh[3]);
                    }
                }
            }
        }
        __syncthreads();   // compute done before staging over pipeline bufs

        // Stage projected tile (+bias) as fp16
#pragma unroll
        for (int nf = 0; nf < 8; ++nf) {
            int col = wn * 64 + nf * 8 + tig * 2;
            float b0 = bias[n0 + col], b1 = bias[n0 + col + 1];
#pragma unroll
            for (int mf = 0; mf < 4; ++mf) {
                int r0 = wm * 64 + mf * 16 + gid;
                *(__half2*)&OTh[r0 * QK_STR + col] =
                    __floats2half2_rn(acc[mf][nf][0] + b0, acc[mf][nf][1] + b1);
                *(__half2*)&OTh[(r0 + 8) * QK_STR + col] =
                    __floats2half2_rn(acc[mf][nf][2] + b0, acc[mf][nf][3] + b1);
            }
        }
        __syncthreads();

        if (wg == 0) {
            // Gram via fp16 MMA: Q-warp wl handles dv = wl and wl+4
#pragma unroll
            for (int dvi = 0; dvi < 2; ++dvi) {
                const int dv = wl + dvi * 4;
#pragma unroll
                for (int kk = 0; kk < 8; ++kk) {
                    const int kb = kk * 16 + tig * 2;
                    uint32_t a[4];
                    a[0] = ldh2(&QTh[(gid * 8 + dv)       * QK_STR + kb]);
                    a[1] = ldh2(&QTh[((gid + 8) * 8 + dv) * QK_STR + kb]);
                    a[2] = ldh2(&QTh[(gid * 8 + dv)       * QK_STR + kb + 8]);
                    a[3] = ldh2(&QTh[((gid + 8) * 8 + dv) * QK_STR + kb + 8]);
                    uint32_t b0 = ldh2(&KTh[(gid * 8 + dv) * QK_STR + kb]);
                    uint32_t b1 = ldh2(&KTh[(gid * 8 + dv) * QK_STR + kb + 8]);
                    mma_f16(Gc[0], a, b0, b1);
                    b0 = ldh2(&KTh[((gid + 8) * 8 + dv) * QK_STR + kb]);
                    b1 = ldh2(&KTh[((gid + 8) * 8 + dv) * QK_STR + kb + 8]);
                    mma_f16(Gc[1], a, b0, b1);
                }
            }
        } else {
            // fro: ||Q||^2 partial (one full row per thread)
            int r = tid - 128;   // 0..127
#pragma unroll 8
            for (int c = 0; c < 64; ++c) {
                __half2 h = *(const __half2*)&QTh[r * QK_STR + 2 * c];
                float2 f = __half22float2(h);
                facc += f.x * f.x + f.y * f.y;
            }
        }
        __syncthreads();
    }

    float* RED  = (float*)((char*)S + K1_REDB_OFF);   // 4 x 256
    float* RED2 = RED + 1024;                          // 128
    if (wg == 0) {
        RED[wl * 256 + gid * 16 + 2 * tig]               = Gc[0][0];
        RED[wl * 256 + gid * 16 + 2 * tig + 1]           = Gc[0][1];
        RED[wl * 256 + (gid + 8) * 16 + 2 * tig]         = Gc[0][2];
        RED[wl * 256 + (gid + 8) * 16 + 2 * tig + 1]     = Gc[0][3];
        RED[wl * 256 + gid * 16 + 8 + 2 * tig]           = Gc[1][0];
        RED[wl * 256 + gid * 16 + 8 + 2 * tig + 1]       = Gc[1][1];
        RED[wl * 256 + (gid + 8) * 16 + 8 + 2 * tig]     = Gc[1][2];
        RED[wl * 256 + (gid + 8) * 16 + 8 + 2 * tig + 1] = Gc[1][3];
    } else {
        RED2[tid - 128] = facc;
    }
    __syncthreads();
    {
        float g = 0.f;
#pragma unroll
        for (int w = 0; w < 4; ++w) g += RED[w * 256 + tid];
        g_part[(size_t)blockIdx.x * PART_STRIDE + tid] = g;
    }
    if (tid < 16) {
        float s = 0.f;
#pragma unroll
        for (int t = 0; t < 8; ++t) s += RED2[tid * 8 + t];
        g_part[(size_t)blockIdx.x * PART_STRIDE + 256 + tid] = s;
    }
}

// ============================================================================
// K2: U = X Wv^T + bv  (fp16 in/out, 256 threads, 4x2 warps of 32x64,
// 3-stage cp.async, 2 CTAs/SM — R13 config).
// Stage: A 0, B 10240; size 20480 (x3 = 61440).
// ============================================================================
#define V_STAGE_B  20480
#define V_BYTES    (3 * V_STAGE_B)

__global__ void __launch_bounds__(256, 2) gemm_v(const float* __restrict__ bias)
{
    extern __shared__ float S[];
    const uint32_t smemu = sptr(S);

    const int tid  = threadIdx.x;
    const int lane = tid & 31;
    const int wid  = tid >> 5;      // 0..7
    const int gid  = lane >> 2;
    const int tig  = lane & 3;
    const int wm   = wid & 3;       // 4 m-tiles x 32 rows
    const int wn   = wid >> 2;      // 2 n-tiles x 64 cols
    const int m0   = blockIdx.y * 128;
    const int n0   = blockIdx.x * 128;

    const int lofsB = (lane & 15) * 80 + ((lane >> 4) << 4);

    float acc[2][8][4];
#pragma unroll
    for (int a = 0; a < 2; a++)
#pragma unroll
        for (int b = 0; b < 8; b++)
#pragma unroll
            for (int c = 0; c < 4; c++) acc[a][b][c] = 0.f;

    auto issue = [&](int kt, int st) {
        uint32_t d0 = smemu + st * V_STAGE_B;
#pragma unroll
        for (int it = 0; it < 2; ++it) {
            int idx = tid + it * 256;       // 0..511
            int cr  = idx >> 2;             // 0..127
            int cc  = (idx & 3) * 16;
            uint32_t d = d0 + cr * 80 + cc;
            size_t xo = (size_t)(m0 + cr) * (DIN * 2) + kt * 64 + cc;
            size_t wo = (size_t)(n0 + cr) * (DIN * 2) + kt * 64 + cc;
            cpa16(d,         (const char*)g_Xh  + xo);
            cpa16(d + 10240, (const char*)g_Wvh + wo);
        }
    };

    issue(0, 0); CP_COMMIT();
    issue(1, 1); CP_COMMIT();
#pragma unroll 1
    for (int kt = 0; kt < 16; ++kt) {
        if (kt < 14) { CP_WAIT1(); } else { CP_WAIT0(); }
        __syncthreads();
        if (kt + 2 < 16) { issue(kt + 2, (kt + 2) % 3); CP_COMMIT(); }
        const uint32_t stage = smemu + (kt % 3) * V_STAGE_B;
        const uint32_t aB = stage + lofsB;
        const uint32_t bB = stage + 10240 + lofsB;
#pragma unroll
        for (int ks = 0; ks < 2; ++ks) {
            const int kb = ks * 32;
            uint32_t ah[2][4];
            ldsm_x4(ah[0], aB + (wm * 32)      * 80 + kb);
            ldsm_x4(ah[1], aB + (wm * 32 + 16) * 80 + kb);
#pragma unroll
            for (int p = 0; p < 4; ++p) {
                uint32_t bh[4];
                ldsm_x4(bh, bB + (wn * 64 + p * 16) * 80 + kb);
#pragma unroll
                for (int mf = 0; mf < 2; ++mf) {
                    mma_f16(acc[mf][2*p],     ah[mf], bh[0], bh[2]);
                    mma_f16(acc[mf][2*p + 1], ah[mf], bh[1], bh[3]);
                }
            }
        }
    }

#pragma unroll
    for (int nf = 0; nf < 8; ++nf) {
        int col = n0 + wn * 64 + nf * 8 + tig * 2;
        float b0 = bias[col];
        float b1 = bias[col + 1];
#pragma unroll
        for (int mf = 0; mf < 2; ++mf) {
            int r0 = m0 + wm * 32 + mf * 16 + gid;
            *(__half2*)(g_Uh + (size_t)r0 * DOUT + col) =
                __floats2half2_rn(acc[mf][nf][0] + b0, acc[mf][nf][1] + b1);
            *(__half2*)(g_Uh + (size_t)(r0 + 8) * DOUT + col) =
                __floats2half2_rn(acc[mf][nf][2] + b0, acc[mf][nf][3] + b1);
        }
    }
}

// ============================================================================
// K3a: pre-reduce partials 1024 -> 64 groups (deterministic)
// ============================================================================
__global__ void __launch_bounds__(288) prereduce_kernel()
{
    int tid = threadIdx.x;
    if (tid >= PART_STRIDE) return;
    int b = blockIdx.x;
    float s = 0.f;
#pragma unroll 4
    for (int c = 0; c < 16; ++c)
        s += g_part[(size_t)(b * 16 + c) * PART_STRIDE + tid];
    g_part2[b * PART_STRIDE + tid] = s;
}

// ============================================================================
// K3b: finalize — reduce 64 groups, sigmoid, dual softmax, 10x projection -> P
// ============================================================================
__global__ void __launch_bounds__(256) finalize_kernel()
{
    __shared__ float Am[256], T[256], FR[256];
    __shared__ float fro[16], m0s[16], s0s[16], m1s[16], s1s[16], red[16], red2[16];
    const int tid = threadIdx.x;
    const int i = tid >> 4, j = tid & 15;

    float a0=0,a1=0,a2=0,a3=0,a4=0,a5=0,a6=0,a7=0;
    for (int c = 0; c < PRE_GROUPS; c += 8) {
        a0 += g_part2[(size_t)(c    ) * PART_STRIDE + tid];
        a1 += g_part2[(size_t)(c + 1) * PART_STRIDE + tid];
        a2 += g_part2[(size_t)(c + 2) * PART_STRIDE + tid];
        a3 += g_part2[(size_t)(c + 3) * PART_STRIDE + tid];
        a4 += g_part2[(size_t)(c + 4) * PART_STRIDE + tid];
        a5 += g_part2[(size_t)(c + 5) * PART_STRIDE + tid];
        a6 += g_part2[(size_t)(c + 6) * PART_STRIDE + tid];
        a7 += g_part2[(size_t)(c + 7) * PART_STRIDE + tid];
    }
    float g = ((a0 + a1) + (a2 + a3)) + ((a4 + a5) + (a6 + a7));

    {
        float s = 0.f;
        for (int c = i * 4; c < i * 4 + 4; ++c)
            s += g_part2[(size_t)c * PART_STRIDE + 256 + j];
        FR[tid] = s;
    }
    __syncthreads();
    if (tid < 16) {
        float s = 0.f;
#pragma unroll
        for (int t = 0; t < 16; ++t) s += FR[t * 16 + tid];
        fro[tid] = sqrtf(s);
    }
    __syncthreads();

    float p0 = 1.f / (1.f + expf(-g / fro[i]));
    Am[tid] = p0;
    __syncthreads();

    if (tid < 16) {
        float m = -1e30f;
        for (int k = 0; k < 16; ++k) m = fmaxf(m, Am[k * 16 + tid]);
        float s = 0.f;
        for (int k = 0; k < 16; ++k) s += expf(Am[k * 16 + tid] - m);
        m0s[tid] = m; s0s[tid] = s;
        float m1 = -1e30f;
        for (int k = 0; k < 16; ++k) m1 = fmaxf(m1, Am[tid * 16 + k]);
        float s1 = 0.f;
        for (int k = 0; k < 16; ++k) s1 += expf(Am[tid * 16 + k] - m1);
        m1s[tid] = m1; s1s[tid] = s1;
    }
    __syncthreads();

    float p = 0.5f * (expf(p0 - m0s[j]) / s0s[j] + expf(p0 - m1s[i]) / s1s[i]);

    for (int it = 0; it < 10; ++it) {
        float p1 = fmaxf(p, 0.f);
        T[tid] = p1;
        __syncthreads();
        if (tid < 16) {
            float s = 0.f;
            for (int k = 0; k < 16; ++k) s += T[tid * 16 + k];
            red[tid] = (s - 1.f) * (1.f / 16.f);
        }
        __syncthreads();
        float p2 = p1 - red[i];
        T[tid] = p2;
        __syncthreads();
        if (tid < 16) {
            float s = 0.f;
            for (int k = 0; k < 16; ++k) s += T[k * 16 + tid];
            red2[tid] = (s - 1.f) * (1.f / 16.f);
        }
        __syncthreads();
        p = p2 - red2[j];
        __syncthreads();
    }
    g_P[tid] = p;
}

// ============================================================================
// K4: out[j] = sum_i P[i,j] * U[i]   (U fp16, fp32 accumulate, fp32 out)
// Register-lean: stream u_i, accumulate y[16]; identical summation order
// (i ascending per output element) to the previous version.
// ============================================================================
__global__ void __launch_bounds__(256) mix_kernel(float* __restrict__ out)
{
    __shared__ float Ps[256];
    Ps[threadIdx.x] = g_P[threadIdx.x];
    __syncthreads();

    size_t n4 = (size_t)blockIdx.x * 256 + threadIdx.x;   // 0..NPER4-1
    const uint2* U2 = (const uint2*)g_Uh;
    float4* O4 = (float4*)out;

    float4 y[16];
#pragma unroll
    for (int jj = 0; jj < 16; ++jj) y[jj] = make_float4(0.f, 0.f, 0.f, 0.f);

#pragma unroll
    for (int i = 0; i < 16; ++i) {
        uint2 h = U2[(size_t)i * NPER4 + n4];
        float2 lo = __half22float2(*(__half2*)&h.x);
        float2 hi = __half22float2(*(__half2*)&h.y);
#pragma unroll
        for (int jj = 0; jj < 16; ++jj) {
            float pv = Ps[i * 16 + jj];
            y[jj].x += pv * lo.x; y[jj].y += pv * lo.y;
            y[jj].z += pv * hi.x; y[jj].w += pv * hi.y;
        }
    }
#pragma unroll
    for (int jj = 0; jj < 16; ++jj)
        O4[(size_t)jj * NPER4 + n4] = y[jj];
}

// -------------------- launch --------------------
extern "C" void kernel_launch(void* const* d_in, const int* in_sizes, int n_in,
                              void* d_out, int out_size)
{
    const float* X   = (const float*)d_in[0];
    const float* WQw = (const float*)d_in[1];
    const float* WQb = (const float*)d_in[2];
    const float* WKw = (const float*)d_in[3];
    const float* WKb = (const float*)d_in[4];
    const float* WVw = (const float*)d_in[5];
    const float* WVb = (const float*)d_in[6];
    float* out = (float*)d_out;

    cudaFuncSetAttribute(qkgram_kernel,
                         cudaFuncAttributeMaxDynamicSharedMemorySize, K1_BYTES);
    cudaFuncSetAttribute(gemm_v,
                         cudaFuncAttributeMaxDynamicSharedMemorySize, V_BYTES);

    // Convert X and weights to fp16 (single launch)
    cvt_all_kernel<<<CVT_XBLKS + 768, 256>>>((const float4*)X,
                                             (const float4*)WQw,
                                             (const float4*)WKw,
                                             (const float4*)WVw);

    // Fused Q/K projections (fp16, 64x64 warp tiles, 3-stage) + Gram + fro
    qkgram_kernel<<<GRAM_CTAS, 256, K1_BYTES>>>(WQb, WKb);

    // U = X Wv^T + bv (fp16 in/out, 32x64 warp tiles, 3-stage, 2 CTAs/SM)
    gemm_v<<<dim3(DOUT / 128, ROWS / 128), 256, V_BYTES>>>(WVb);

    // P
    prereduce_kernel<<<PRE_GROUPS, 288>>>();
    finalize_kernel<<<1, 256>>>();

    // out[j] = sum_i P[ij] U[i]
    mix_kernel<<<NPER4 / 256, 256>>>(out);
}